// round 12
// baseline (speedup 1.0000x reference)
#include <cuda_runtime.h>
#include <cuda_bf16.h>
#include <cstdint>

// ---------------------------------------------------------------------------
// SCCN forward: 4 ranks, C=128, L=2 layers, sigmoid update, softmax head.
// R10: gemm_mma restructured for 8 independent mma chains/warp (4 n-blocks in
//      flight); sigmoid fused into GEMM A-load / head (g_x + sigmoid_k gone).
// ---------------------------------------------------------------------------

#define C128 128

static const int N0 = 40000, N1 = 120000, N2 = 80000, N3 = 20000;
static const int NTOT = 260000;
static const int YROWS = 720000;

__device__ float g_m[(size_t)NTOT * C128];
__device__ float g_y[(size_t)YROWS * C128];

// ------------------------- helpers -----------------------------------------
__device__ __forceinline__ uint32_t f2tf32(float f) {
    uint32_t r;
    asm("cvt.rna.tf32.f32 %0, %1;" : "=r"(r) : "f"(f));
    return r;
}

// m16n8k8 tf32 mma, C/D fp32. A row-major frag, B col-major frag.
__device__ __forceinline__ void mma_tf32(float* c, const uint32_t* a,
                                         uint32_t b0, uint32_t b1) {
    asm volatile(
        "mma.sync.aligned.m16n8k8.row.col.f32.tf32.tf32.f32 "
        "{%0,%1,%2,%3}, {%4,%5,%6,%7}, {%8,%9}, {%0,%1,%2,%3};"
        : "+f"(c[0]), "+f"(c[1]), "+f"(c[2]), "+f"(c[3])
        : "r"(a[0]), "r"(a[1]), "r"(a[2]), "r"(a[3]), "r"(b0), "r"(b1));
}

// ---------------------------------------------------------------------------
// gemm_mma: for source X[M x 128], compute Y_c = X @ W_c for c < nc (nc<=3).
// Optional fused sigmoid on the A operand (X := sigmoid(X)).
// Persistent CTAs. W chunks staged once per CTA in smem, pre-packed so a B
// fragment (b0=B[k][n], b1=B[k+4][n]) is one conflict-free LDS.64:
//   sWp[c][(kc*4+q)*132 + n] = { W[kc*8+q][n], W[kc*8+q+4][n] }   (float2)
// Block = 256 thr / 8 warps; 256-row tiles; warp covers 32 rows (2 m16
// row-blocks); inner loop holds 4 n-blocks live -> 8 independent mma chains.
// ---------------------------------------------------------------------------
#define WCHUNK (64 * 132)  // float2 elements per weight chunk

__global__ void __launch_bounds__(256) gemm_mma(
    const float* __restrict__ X, int M, int nc, int sig,
    const float* __restrict__ W0, const float* __restrict__ W1,
    const float* __restrict__ W2,
    float* __restrict__ Y0, float* __restrict__ Y1, float* __restrict__ Y2) {
    extern __shared__ __align__(16) float2 sWp[];
    const float* Ws[3] = {W0, W1, W2};
    float* Ys[3] = {Y0, Y1, Y2};
    const int t = threadIdx.x;

    // stage weights (once per CTA; persistent tile loop follows)
    for (int c = 0; c < nc; c++) {
        const float* W = Ws[c];
        float2* dst = sWp + c * WCHUNK;
        for (int i = t; i < 8192; i += 256) {
            int kcq = i >> 7, n = i & 127;
            int k_lo = (kcq >> 2) * 8 + (kcq & 3);
            float2 v;
            v.x = __uint_as_float(f2tf32(__ldg(W + k_lo * C128 + n)));
            v.y = __uint_as_float(f2tf32(__ldg(W + (k_lo + 4) * C128 + n)));
            dst[kcq * 132 + n] = v;
        }
    }
    __syncthreads();

    const int lane = t & 31, wid = t >> 5;
    const int q = lane & 3, p = lane >> 2;
    const int tiles = (M + 255) >> 8;

    for (int tile = blockIdx.x; tile < tiles; tile += gridDim.x) {
        const int rbase = (tile << 8) + (wid << 5);
        const int r0 = rbase + p;
        const int rr[4] = {r0, r0 + 8, r0 + 16, r0 + 24};
        const bool g[4] = {rr[0] < M, rr[1] < M, rr[2] < M, rr[3] < M};

        // A fragments: 2 row-blocks x 16 k-chunks x 4 regs = 128 regs
        uint32_t A[2][16][4];
#pragma unroll
        for (int b = 0; b < 2; b++) {
            const float* x0 = X + (size_t)rr[b * 2] * C128 + q;
            const float* x1 = X + (size_t)rr[b * 2 + 1] * C128 + q;
#pragma unroll
            for (int kc = 0; kc < 16; kc++) {
                int col = kc * 8;
                float v00 = g[b * 2]     ? __ldg(x0 + col)     : 0.f;
                float v10 = g[b * 2 + 1] ? __ldg(x1 + col)     : 0.f;
                float v01 = g[b * 2]     ? __ldg(x0 + col + 4) : 0.f;
                float v11 = g[b * 2 + 1] ? __ldg(x1 + col + 4) : 0.f;
                if (sig) {
                    v00 = 1.f / (1.f + __expf(-v00));
                    v10 = 1.f / (1.f + __expf(-v10));
                    v01 = 1.f / (1.f + __expf(-v01));
                    v11 = 1.f / (1.f + __expf(-v11));
                }
                A[b][kc][0] = f2tf32(v00);
                A[b][kc][1] = f2tf32(v10);
                A[b][kc][2] = f2tf32(v01);
                A[b][kc][3] = f2tf32(v11);
            }
        }

#pragma unroll 1
        for (int c = 0; c < nc; c++) {
            const float2* Wp = sWp + c * WCHUNK;
            float* Y = Ys[c];
#pragma unroll 1
            for (int n0 = 0; n0 < 128; n0 += 32) {   // 4 n-blocks per pass
                float acc[2][4][4];
#pragma unroll
                for (int b = 0; b < 2; b++)
#pragma unroll
                    for (int j = 0; j < 4; j++)
#pragma unroll
                        for (int s = 0; s < 4; s++) acc[b][j][s] = 0.f;

#pragma unroll
                for (int kc = 0; kc < 16; kc++) {
                    const float2* wrow = Wp + (kc * 4 + q) * 132 + n0 + p;
                    uint32_t b0[4], b1[4];
#pragma unroll
                    for (int j = 0; j < 4; j++) {
                        float2 bb = wrow[j * 8];
                        b0[j] = __float_as_uint(bb.x);
                        b1[j] = __float_as_uint(bb.y);
                    }
#pragma unroll
                    for (int j = 0; j < 4; j++) {
                        mma_tf32(acc[0][j], A[0][kc], b0[j], b1[j]);
                        mma_tf32(acc[1][j], A[1][kc], b0[j], b1[j]);
                    }
                }

#pragma unroll
                for (int j = 0; j < 4; j++) {
                    const int col = n0 + j * 8 + q * 2;
                    if (g[0]) *(float2*)(Y + (size_t)rr[0] * C128 + col) =
                                  make_float2(acc[0][j][0], acc[0][j][1]);
                    if (g[1]) *(float2*)(Y + (size_t)rr[1] * C128 + col) =
                                  make_float2(acc[0][j][2], acc[0][j][3]);
                    if (g[2]) *(float2*)(Y + (size_t)rr[2] * C128 + col) =
                                  make_float2(acc[1][j][0], acc[1][j][1]);
                    if (g[3]) *(float2*)(Y + (size_t)rr[3] * C128 + col) =
                                  make_float2(acc[1][j][2], acc[1][j][3]);
                }
            }
        }
    }
}

// ---------------------------------------------------------------------------
// COO SPMM scatter: O[rows[e]] += vals[e] * Y[cols[e]]  (warp per nnz)
// ---------------------------------------------------------------------------
__global__ void __launch_bounds__(256) spmm_acc(const int* __restrict__ rows,
                                                const int* __restrict__ cols,
                                                const float* __restrict__ vals,
                                                int nnz,
                                                const float* __restrict__ Y,
                                                float* __restrict__ O) {
    int gthr = blockIdx.x * blockDim.x + threadIdx.x;
    int e = gthr >> 5;
    if (e >= nnz) return;
    int lane = gthr & 31;
    int r = __ldg(rows + e);
    int c = __ldg(cols + e);
    float v = __ldg(vals + e);
    float4 a = *(const float4*)(Y + (size_t)c * C128 + lane * 4);
    a.x *= v; a.y *= v; a.z *= v; a.w *= v;
    float* dst = O + (size_t)r * C128 + lane * 4;
    asm volatile("red.global.add.v4.f32 [%0], {%1, %2, %3, %4};"
                 :: "l"(dst), "f"(a.x), "f"(a.y), "f"(a.z), "f"(a.w)
                 : "memory");
}

// ---------------------------------------------------------------------------
// Head: out = softmax(sigmoid(M0) @ Wout + b). One warp per row.
// ---------------------------------------------------------------------------
__global__ void __launch_bounds__(256) head_k(const float* __restrict__ X,
                                              const float* __restrict__ Wout,
                                              const float* __restrict__ bout,
                                              float* __restrict__ out, int M) {
    __shared__ float sW[128 * 10];
    __shared__ float sb[10];
    int t = threadIdx.x;
    for (int i = t; i < 1280; i += blockDim.x) sW[i] = Wout[i];
    if (t < 10) sb[t] = bout[t];
    __syncthreads();

    int warp = (blockIdx.x * blockDim.x + t) >> 5;
    int lane = t & 31;
    if (warp >= M) return;

    const float* xr = X + (size_t)warp * C128;
    float acc[10];
#pragma unroll
    for (int j = 0; j < 10; j++) acc[j] = 0.f;
#pragma unroll
    for (int i = 0; i < 4; i++) {
        int k = lane + 32 * i;
        float xv = __ldg(xr + k);
        xv = 1.f / (1.f + __expf(-xv));   // fused sigmoid
#pragma unroll
        for (int j = 0; j < 10; j++) acc[j] = fmaf(xv, sW[k * 10 + j], acc[j]);
    }
#pragma unroll
    for (int j = 0; j < 10; j++) {
#pragma unroll
        for (int o = 16; o > 0; o >>= 1)
            acc[j] += __shfl_down_sync(0xffffffffu, acc[j], o);
    }
    if (lane == 0) {
        float mx = -1e30f;
#pragma unroll
        for (int j = 0; j < 10; j++) { acc[j] += sb[j]; mx = fmaxf(mx, acc[j]); }
        float s = 0.f;
#pragma unroll
        for (int j = 0; j < 10; j++) { acc[j] = __expf(acc[j] - mx); s += acc[j]; }
        float inv = 1.f / s;
#pragma unroll
        for (int j = 0; j < 10; j++) out[(size_t)warp * 10 + j] = acc[j] * inv;
    }
}

// ---------------------------------------------------------------------------
// Host orchestration
// ---------------------------------------------------------------------------
extern "C" void kernel_launch(void* const* d_in, const int* in_sizes, int n_in,
                              void* d_out, int out_size) {
    const int N[4]      = {N0, N1, N2, N3};
    const int ROWOFF[4] = {0, 40000, 160000, 240000};
    const int ADJNNZ[4] = {320000, 960000, 640000, 160000};
    const int INCNNZ[3] = {240000, 240000, 80000};

    const int SAME_OFF[4] = {0, 40000, 160000, 240000};
    const int H2L_OFF[3]  = {260000, 380000, 460000};  // rank r h2l (from x_{r+1})
    const int L2H_OFF[3]  = {480000, 520000, 640000};  // rank r+1 l2h (from x_r)

    const float* x_in[4] = {(const float*)d_in[0], (const float*)d_in[1],
                            (const float*)d_in[2], (const float*)d_in[3]};
    const int*   adj_row[4]; const int* adj_col[4]; const float* adj_val[4];
    for (int r = 0; r < 4; r++) {
        adj_row[r] = (const int*)d_in[4 + 3 * r];
        adj_col[r] = (const int*)d_in[5 + 3 * r];
        adj_val[r] = (const float*)d_in[6 + 3 * r];
    }
    const int* inc_row[3]; const int* inc_col[3]; const float* inc_val[3];
    for (int i = 0; i < 3; i++) {
        inc_row[i] = (const int*)d_in[16 + 3 * i];
        inc_col[i] = (const int*)d_in[17 + 3 * i];
        inc_val[i] = (const float*)d_in[18 + 3 * i];
    }
    const float* W_same = (const float*)d_in[25];
    const float* W_h2l  = (const float*)d_in[26];
    const float* W_l2h  = (const float*)d_in[27];
    const float* W_out  = (const float*)d_in[28];
    const float* b_out  = (const float*)d_in[29];
    float* out = (float*)d_out;

    float *gm, *gy;
    cudaGetSymbolAddress((void**)&gm, g_m);
    cudaGetSymbolAddress((void**)&gy, g_y);

    const int MAX_SMEM = 3 * WCHUNK * (int)sizeof(float2);  // 202752 B
    cudaFuncSetAttribute(gemm_mma, cudaFuncAttributeMaxDynamicSharedMemorySize,
                         MAX_SMEM);

    const int WMAT = 128 * 128;
    auto launch = [&](const float* X, int M, int nc, int sig,
                      const float* w0, const float* w1, const float* w2,
                      float* y0, float* y1, float* y2) {
        int tiles = (M + 255) / 256;
        int grid = tiles < 148 ? tiles : 148;
        gemm_mma<<<grid, 256, nc * WCHUNK * (int)sizeof(float2)>>>(
            X, M, nc, sig, w0, w1, w2, y0, y1, y2);
    };

    for (int l = 0; l < 2; l++) {
        const float* xs[4];
        int sig = (l == 0) ? 0 : 1;  // layer-2 inputs are sigmoid(g_m)
        for (int r = 0; r < 4; r++)
            xs[r] = (l == 0) ? x_in[r] : (gm + (size_t)ROWOFF[r] * C128);

        // phase A: weight-concatenated GEMMs, one launch per source rank
        launch(xs[0], N[0], 2, sig,
               W_same + (size_t)(l * 4 + 0) * WMAT,
               W_l2h  + (size_t)(l * 3 + 0) * WMAT, nullptr,
               gy + (size_t)SAME_OFF[0] * C128,
               gy + (size_t)L2H_OFF[0] * C128, nullptr);
        launch(xs[1], N[1], 3, sig,
               W_same + (size_t)(l * 4 + 1) * WMAT,
               W_h2l  + (size_t)(l * 3 + 0) * WMAT,
               W_l2h  + (size_t)(l * 3 + 1) * WMAT,
               gy + (size_t)SAME_OFF[1] * C128,
               gy + (size_t)H2L_OFF[0] * C128,
               gy + (size_t)L2H_OFF[1] * C128);
        launch(xs[2], N[2], 3, sig,
               W_same + (size_t)(l * 4 + 2) * WMAT,
               W_h2l  + (size_t)(l * 3 + 1) * WMAT,
               W_l2h  + (size_t)(l * 3 + 2) * WMAT,
               gy + (size_t)SAME_OFF[2] * C128,
               gy + (size_t)H2L_OFF[1] * C128,
               gy + (size_t)L2H_OFF[2] * C128);
        launch(xs[3], N[3], 2, sig,
               W_same + (size_t)(l * 4 + 3) * WMAT,
               W_h2l  + (size_t)(l * 3 + 2) * WMAT, nullptr,
               gy + (size_t)SAME_OFF[3] * C128,
               gy + (size_t)H2L_OFF[2] * C128, nullptr);

        // phase B: zero accumulator (GEMMs above already consumed g_m)
        cudaMemsetAsync(gm, 0, (size_t)NTOT * C128 * sizeof(float));

        // phase C: scatter-add SPMMs
        for (int r = 0; r < 4; r++) {
            int blocks = (ADJNNZ[r] * 32 + 255) / 256;
            spmm_acc<<<blocks, 256>>>(adj_row[r], adj_col[r], adj_val[r],
                                      ADJNNZ[r],
                                      gy + (size_t)SAME_OFF[r] * C128,
                                      gm + (size_t)ROWOFF[r] * C128);
        }
        for (int r = 0; r < 3; r++) {
            int blocks = (INCNNZ[r] * 32 + 255) / 256;
            spmm_acc<<<blocks, 256>>>(inc_row[r], inc_col[r], inc_val[r],
                                      INCNNZ[r],
                                      gy + (size_t)H2L_OFF[r] * C128,
                                      gm + (size_t)ROWOFF[r] * C128);
        }
        for (int r = 1; r < 4; r++) {
            int i = r - 1;
            int blocks = (INCNNZ[i] * 32 + 255) / 256;
            spmm_acc<<<blocks, 256>>>(inc_col[i], inc_row[i], inc_val[i],
                                      INCNNZ[i],
                                      gy + (size_t)L2H_OFF[i] * C128,
                                      gm + (size_t)ROWOFF[r] * C128);
        }
    }

    // head: softmax(sigmoid(m0) @ W_out + b_out)
    int blocks = (N0 * 32 + 255) / 256;
    head_k<<<blocks, 256>>>(gm, W_out, b_out, out, N0);
}

// round 13
// speedup vs baseline: 1.2975x; 1.2975x over previous
#include <cuda_runtime.h>
#include <cuda_bf16.h>
#include <cstdint>

// ---------------------------------------------------------------------------
// SCCN forward: 4 ranks, C=128, L=2 layers, sigmoid update, softmax head.
// R13: occupancy-first GEMM. One weight per launch (67.6KB smem), 16 rows per
//      warp (A=64 regs), 4 n-blocks in flight, __launch_bounds__(256,2) ->
//      2 CTAs/SM, 16 warps/SM, 4 independent mma chains per warp.
//      Sigmoid stays fused into layer-2 GEMM A-load and the head.
// ---------------------------------------------------------------------------

#define C128 128

static const int N0 = 40000, N1 = 120000, N2 = 80000, N3 = 20000;
static const int NTOT = 260000;
static const int YROWS = 720000;

__device__ float g_m[(size_t)NTOT * C128];
__device__ float g_y[(size_t)YROWS * C128];

// ------------------------- helpers -----------------------------------------
__device__ __forceinline__ uint32_t f2tf32(float f) {
    uint32_t r;
    asm("cvt.rna.tf32.f32 %0, %1;" : "=r"(r) : "f"(f));
    return r;
}

// m16n8k8 tf32 mma, C/D fp32. A row-major frag, B col-major frag.
__device__ __forceinline__ void mma_tf32(float* c, const uint32_t* a,
                                         uint32_t b0, uint32_t b1) {
    asm volatile(
        "mma.sync.aligned.m16n8k8.row.col.f32.tf32.tf32.f32 "
        "{%0,%1,%2,%3}, {%4,%5,%6,%7}, {%8,%9}, {%0,%1,%2,%3};"
        : "+f"(c[0]), "+f"(c[1]), "+f"(c[2]), "+f"(c[3])
        : "r"(a[0]), "r"(a[1]), "r"(a[2]), "r"(a[3]), "r"(b0), "r"(b1));
}

// ---------------------------------------------------------------------------
// gemm_mma: Y = (sig ? sigmoid(X) : X) @ W   for X[M x 128], W[128 x 128].
// W staged once per CTA in smem as tf32, pre-packed so a B fragment
// (b0=B[k][n], b1=B[k+4][n]) is one conflict-free LDS.64:
//   sWp[(kc*4+q)*132 + n] = { W[kc*8+q][n], W[kc*8+q+4][n] }    (float2)
// Block = 256 thr / 8 warps; 128-row tiles; warp covers 16 rows (1 m16
// block, A = 64 regs); 4 n-blocks live -> 4 independent mma chains.
// ---------------------------------------------------------------------------
#define WCHUNK (64 * 132)  // float2 elements for one packed weight

__global__ void __launch_bounds__(256, 2) gemm_mma(
    const float* __restrict__ X, int M, int sig,
    const float* __restrict__ W, float* __restrict__ Y) {
    extern __shared__ __align__(16) float2 sWp[];
    const int t = threadIdx.x;

    // stage weight (once per CTA; persistent tile loop follows)
    for (int i = t; i < 8192; i += 256) {
        int kcq = i >> 7, n = i & 127;
        int k_lo = (kcq >> 2) * 8 + (kcq & 3);
        float2 v;
        v.x = __uint_as_float(f2tf32(__ldg(W + k_lo * C128 + n)));
        v.y = __uint_as_float(f2tf32(__ldg(W + (k_lo + 4) * C128 + n)));
        sWp[kcq * 132 + n] = v;
    }
    __syncthreads();

    const int lane = t & 31, wid = t >> 5;
    const int q = lane & 3, p = lane >> 2;
    const int tiles = (M + 127) >> 7;

    for (int tile = blockIdx.x; tile < tiles; tile += gridDim.x) {
        const int r0 = (tile << 7) + (wid << 4) + p;   // rows r0, r0+8
        const bool g0 = r0 < M, g1 = (r0 + 8) < M;

        // A fragments: 16 k-chunks x 4 regs = 64 regs
        uint32_t A[16][4];
        {
            const float* x0 = X + (size_t)r0 * C128 + q;
            const float* x1 = x0 + 8 * C128;
#pragma unroll
            for (int kc = 0; kc < 16; kc++) {
                int col = kc * 8;
                float v0 = g0 ? __ldg(x0 + col)     : 0.f;
                float v1 = g1 ? __ldg(x1 + col)     : 0.f;
                float v2 = g0 ? __ldg(x0 + col + 4) : 0.f;
                float v3 = g1 ? __ldg(x1 + col + 4) : 0.f;
                if (sig) {
                    v0 = 1.f / (1.f + __expf(-v0));
                    v1 = 1.f / (1.f + __expf(-v1));
                    v2 = 1.f / (1.f + __expf(-v2));
                    v3 = 1.f / (1.f + __expf(-v3));
                }
                A[kc][0] = f2tf32(v0);
                A[kc][1] = f2tf32(v1);
                A[kc][2] = f2tf32(v2);
                A[kc][3] = f2tf32(v3);
            }
        }

#pragma unroll 1
        for (int n0 = 0; n0 < 128; n0 += 32) {   // 4 n-blocks in flight
            float acc[4][4];
#pragma unroll
            for (int j = 0; j < 4; j++)
#pragma unroll
                for (int s = 0; s < 4; s++) acc[j][s] = 0.f;

#pragma unroll
            for (int kc = 0; kc < 16; kc++) {
                const float2* wrow = sWp + (kc * 4 + q) * 132 + n0 + p;
#pragma unroll
                for (int j = 0; j < 4; j++) {
                    float2 bb = wrow[j * 8];
                    mma_tf32(acc[j], A[kc], __float_as_uint(bb.x),
                             __float_as_uint(bb.y));
                }
            }

#pragma unroll
            for (int j = 0; j < 4; j++) {
                const int col = n0 + j * 8 + q * 2;
                if (g0) *(float2*)(Y + (size_t)r0 * C128 + col) =
                            make_float2(acc[j][0], acc[j][1]);
                if (g1) *(float2*)(Y + (size_t)(r0 + 8) * C128 + col) =
                            make_float2(acc[j][2], acc[j][3]);
            }
        }
    }
}

// ---------------------------------------------------------------------------
// COO SPMM scatter: O[rows[e]] += vals[e] * Y[cols[e]]  (warp per nnz)
// ---------------------------------------------------------------------------
__global__ void __launch_bounds__(256) spmm_acc(const int* __restrict__ rows,
                                                const int* __restrict__ cols,
                                                const float* __restrict__ vals,
                                                int nnz,
                                                const float* __restrict__ Y,
                                                float* __restrict__ O) {
    int gthr = blockIdx.x * blockDim.x + threadIdx.x;
    int e = gthr >> 5;
    if (e >= nnz) return;
    int lane = gthr & 31;
    int r = __ldg(rows + e);
    int c = __ldg(cols + e);
    float v = __ldg(vals + e);
    float4 a = *(const float4*)(Y + (size_t)c * C128 + lane * 4);
    a.x *= v; a.y *= v; a.z *= v; a.w *= v;
    float* dst = O + (size_t)r * C128 + lane * 4;
    asm volatile("red.global.add.v4.f32 [%0], {%1, %2, %3, %4};"
                 :: "l"(dst), "f"(a.x), "f"(a.y), "f"(a.z), "f"(a.w)
                 : "memory");
}

// ---------------------------------------------------------------------------
// Head: out = softmax(sigmoid(M0) @ Wout + b). One warp per row.
// ---------------------------------------------------------------------------
__global__ void __launch_bounds__(256) head_k(const float* __restrict__ X,
                                              const float* __restrict__ Wout,
                                              const float* __restrict__ bout,
                                              float* __restrict__ out, int M) {
    __shared__ float sW[128 * 10];
    __shared__ float sb[10];
    int t = threadIdx.x;
    for (int i = t; i < 1280; i += blockDim.x) sW[i] = Wout[i];
    if (t < 10) sb[t] = bout[t];
    __syncthreads();

    int warp = (blockIdx.x * blockDim.x + t) >> 5;
    int lane = t & 31;
    if (warp >= M) return;

    const float* xr = X + (size_t)warp * C128;
    float acc[10];
#pragma unroll
    for (int j = 0; j < 10; j++) acc[j] = 0.f;
#pragma unroll
    for (int i = 0; i < 4; i++) {
        int k = lane + 32 * i;
        float xv = __ldg(xr + k);
        xv = 1.f / (1.f + __expf(-xv));   // fused sigmoid
#pragma unroll
        for (int j = 0; j < 10; j++) acc[j] = fmaf(xv, sW[k * 10 + j], acc[j]);
    }
#pragma unroll
    for (int j = 0; j < 10; j++) {
#pragma unroll
        for (int o = 16; o > 0; o >>= 1)
            acc[j] += __shfl_down_sync(0xffffffffu, acc[j], o);
    }
    if (lane == 0) {
        float mx = -1e30f;
#pragma unroll
        for (int j = 0; j < 10; j++) { acc[j] += sb[j]; mx = fmaxf(mx, acc[j]); }
        float s = 0.f;
#pragma unroll
        for (int j = 0; j < 10; j++) { acc[j] = __expf(acc[j] - mx); s += acc[j]; }
        float inv = 1.f / s;
#pragma unroll
        for (int j = 0; j < 10; j++) out[(size_t)warp * 10 + j] = acc[j] * inv;
    }
}

// ---------------------------------------------------------------------------
// Host orchestration
// ---------------------------------------------------------------------------
extern "C" void kernel_launch(void* const* d_in, const int* in_sizes, int n_in,
                              void* d_out, int out_size) {
    const int N[4]      = {N0, N1, N2, N3};
    const int ROWOFF[4] = {0, 40000, 160000, 240000};
    const int ADJNNZ[4] = {320000, 960000, 640000, 160000};
    const int INCNNZ[3] = {240000, 240000, 80000};

    const int SAME_OFF[4] = {0, 40000, 160000, 240000};
    const int H2L_OFF[3]  = {260000, 380000, 460000};  // rank r h2l (from x_{r+1})
    const int L2H_OFF[3]  = {480000, 520000, 640000};  // rank r+1 l2h (from x_r)

    const float* x_in[4] = {(const float*)d_in[0], (const float*)d_in[1],
                            (const float*)d_in[2], (const float*)d_in[3]};
    const int*   adj_row[4]; const int* adj_col[4]; const float* adj_val[4];
    for (int r = 0; r < 4; r++) {
        adj_row[r] = (const int*)d_in[4 + 3 * r];
        adj_col[r] = (const int*)d_in[5 + 3 * r];
        adj_val[r] = (const float*)d_in[6 + 3 * r];
    }
    const int* inc_row[3]; const int* inc_col[3]; const float* inc_val[3];
    for (int i = 0; i < 3; i++) {
        inc_row[i] = (const int*)d_in[16 + 3 * i];
        inc_col[i] = (const int*)d_in[17 + 3 * i];
        inc_val[i] = (const float*)d_in[18 + 3 * i];
    }
    const float* W_same = (const float*)d_in[25];
    const float* W_h2l  = (const float*)d_in[26];
    const float* W_l2h  = (const float*)d_in[27];
    const float* W_out  = (const float*)d_in[28];
    const float* b_out  = (const float*)d_in[29];
    float* out = (float*)d_out;

    float *gm, *gy;
    cudaGetSymbolAddress((void**)&gm, g_m);
    cudaGetSymbolAddress((void**)&gy, g_y);

    const int GSMEM = WCHUNK * (int)sizeof(float2);  // 67584 B
    cudaFuncSetAttribute(gemm_mma, cudaFuncAttributeMaxDynamicSharedMemorySize,
                         GSMEM);

    const int WMAT = 128 * 128;
    auto launch = [&](const float* X, int M, int sig, const float* w,
                      float* y) {
        int tiles = (M + 127) / 128;
        int grid = tiles < 296 ? tiles : 296;   // 2 CTAs/SM
        gemm_mma<<<grid, 256, GSMEM>>>(X, M, sig, w, y);
    };

    for (int l = 0; l < 2; l++) {
        const float* xs[4];
        int sig = (l == 0) ? 0 : 1;  // layer-2 inputs are sigmoid(g_m)
        for (int r = 0; r < 4; r++)
            xs[r] = (l == 0) ? x_in[r] : (gm + (size_t)ROWOFF[r] * C128);

        // phase A: 10 GEMMs, one weight each
        for (int r = 0; r < 4; r++)
            launch(xs[r], N[r], sig, W_same + (size_t)(l * 4 + r) * WMAT,
                   gy + (size_t)SAME_OFF[r] * C128);
        for (int r = 0; r < 3; r++)   // h2l for rank r uses x_{r+1}
            launch(xs[r + 1], N[r + 1], sig, W_h2l + (size_t)(l * 3 + r) * WMAT,
                   gy + (size_t)H2L_OFF[r] * C128);
        for (int r = 1; r < 4; r++)   // l2h for rank r uses x_{r-1}
            launch(xs[r - 1], N[r - 1], sig,
                   W_l2h + (size_t)(l * 3 + (r - 1)) * WMAT,
                   gy + (size_t)L2H_OFF[r - 1] * C128);

        // phase B: zero accumulator (GEMMs above already consumed g_m)
        cudaMemsetAsync(gm, 0, (size_t)NTOT * C128 * sizeof(float));

        // phase C: scatter-add SPMMs
        for (int r = 0; r < 4; r++) {
            int blocks = (ADJNNZ[r] * 32 + 255) / 256;
            spmm_acc<<<blocks, 256>>>(adj_row[r], adj_col[r], adj_val[r],
                                      ADJNNZ[r],
                                      gy + (size_t)SAME_OFF[r] * C128,
                                      gm + (size_t)ROWOFF[r] * C128);
        }
        for (int r = 0; r < 3; r++) {
            int blocks = (INCNNZ[r] * 32 + 255) / 256;
            spmm_acc<<<blocks, 256>>>(inc_row[r], inc_col[r], inc_val[r],
                                      INCNNZ[r],
                                      gy + (size_t)H2L_OFF[r] * C128,
                                      gm + (size_t)ROWOFF[r] * C128);
        }
        for (int r = 1; r < 4; r++) {
            int i = r - 1;
            int blocks = (INCNNZ[i] * 32 + 255) / 256;
            spmm_acc<<<blocks, 256>>>(inc_col[i], inc_row[i], inc_val[i],
                                      INCNNZ[i],
                                      gy + (size_t)L2H_OFF[i] * C128,
                                      gm + (size_t)ROWOFF[r] * C128);
        }
    }

    // head: softmax(sigmoid(m0) @ W_out + b_out)
    int blocks = (N0 * 32 + 255) / 256;
    head_k<<<blocks, 256>>>(gm, W_out, b_out, out, N0);
}

// round 14
// speedup vs baseline: 1.5271x; 1.1770x over previous
#include <cuda_runtime.h>
#include <cuda_bf16.h>
#include <cstdint>

// ---------------------------------------------------------------------------
// SCCN forward: 4 ranks, C=128, L=2 layers, sigmoid update, softmax head.
// R14: ALL 10 GEMMs of a layer fused into ONE persistent launch (job table +
//      contiguous tile chunks; weight re-staged only at job boundaries).
//      Per-tile math identical to R13 (16 rows/warp, 4 mma chains).
// ---------------------------------------------------------------------------

#define C128 128

static const int N0 = 40000, N1 = 120000, N2 = 80000, N3 = 20000;
static const int NTOT = 260000;
static const int YROWS = 720000;

__device__ float g_m[(size_t)NTOT * C128];
__device__ float g_y[(size_t)YROWS * C128];

// ------------------------- helpers -----------------------------------------
__device__ __forceinline__ uint32_t f2tf32(float f) {
    uint32_t r;
    asm("cvt.rna.tf32.f32 %0, %1;" : "=r"(r) : "f"(f));
    return r;
}

// m16n8k8 tf32 mma, C/D fp32. A row-major frag, B col-major frag.
__device__ __forceinline__ void mma_tf32(float* c, const uint32_t* a,
                                         uint32_t b0, uint32_t b1) {
    asm volatile(
        "mma.sync.aligned.m16n8k8.row.col.f32.tf32.tf32.f32 "
        "{%0,%1,%2,%3}, {%4,%5,%6,%7}, {%8,%9}, {%0,%1,%2,%3};"
        : "+f"(c[0]), "+f"(c[1]), "+f"(c[2]), "+f"(c[3])
        : "r"(a[0]), "r"(a[1]), "r"(a[2]), "r"(a[3]), "r"(b0), "r"(b1));
}

// ---------------------------------------------------------------------------
// Fused GEMM phase: job table of up to 10 GEMMs Y = (sig? sigmoid(X):X) @ W.
// Global tile space; CTA takes a contiguous chunk; weight staged into smem
// only when the chunk crosses a job boundary.
// Packed weight layout (conflict-free LDS.64 B fragments):
//   sWp[(kc*4+q)*132 + n] = { W[kc*8+q][n], W[kc*8+q+4][n] }    (float2)
// ---------------------------------------------------------------------------
#define WCHUNK (64 * 132)  // float2 elements for one packed weight

struct GemmJob {
    const float* X;
    const float* W;
    float* Y;
    int M;
    int tile0;  // first global tile of this job
};
struct GemmJobs {
    GemmJob j[10];
    int njobs;
    int tot;   // total tiles
    int sig;
};

__global__ void __launch_bounds__(256, 2) gemm_all(GemmJobs P) {
    extern __shared__ __align__(16) float2 sWp[];
    const int t = threadIdx.x;
    const int lane = t & 31, wid = t >> 5;
    const int q = lane & 3, p = lane >> 2;

    const int per = (P.tot + gridDim.x - 1) / gridDim.x;
    const int c0 = blockIdx.x * per;
    const int c1 = min(c0 + per, P.tot);
    if (c0 >= c1) return;

    int cur = -1;
    for (int tt = c0; tt < c1; tt++) {
        // resolve job (tile0 ascending)
        int j = (cur < 0) ? 0 : cur;
        while (j + 1 < P.njobs && tt >= P.j[j + 1].tile0) j++;
        if (j != cur) {
            __syncthreads();  // all warps done reading previous weight
            const float* W = P.j[j].W;
            for (int i = t; i < 8192; i += 256) {
                int kcq = i >> 7, n = i & 127;
                int k_lo = (kcq >> 2) * 8 + (kcq & 3);
                float2 v;
                v.x = __uint_as_float(f2tf32(__ldg(W + k_lo * C128 + n)));
                v.y = __uint_as_float(f2tf32(__ldg(W + (k_lo + 4) * C128 + n)));
                sWp[kcq * 132 + n] = v;
            }
            __syncthreads();
            cur = j;
        }
        const GemmJob& job = P.j[j];
        const int M = job.M;
        const int tile = tt - job.tile0;
        const int r0 = (tile << 7) + (wid << 4) + p;   // rows r0, r0+8
        const bool g0 = r0 < M, g1 = (r0 + 8) < M;

        // A fragments: 16 k-chunks x 4 regs = 64 regs
        uint32_t A[16][4];
        {
            const float* x0 = job.X + (size_t)r0 * C128 + q;
            const float* x1 = x0 + 8 * C128;
#pragma unroll
            for (int kc = 0; kc < 16; kc++) {
                int col = kc * 8;
                float v0 = g0 ? __ldg(x0 + col)     : 0.f;
                float v1 = g1 ? __ldg(x1 + col)     : 0.f;
                float v2 = g0 ? __ldg(x0 + col + 4) : 0.f;
                float v3 = g1 ? __ldg(x1 + col + 4) : 0.f;
                if (P.sig) {
                    v0 = 1.f / (1.f + __expf(-v0));
                    v1 = 1.f / (1.f + __expf(-v1));
                    v2 = 1.f / (1.f + __expf(-v2));
                    v3 = 1.f / (1.f + __expf(-v3));
                }
                A[kc][0] = f2tf32(v0);
                A[kc][1] = f2tf32(v1);
                A[kc][2] = f2tf32(v2);
                A[kc][3] = f2tf32(v3);
            }
        }

#pragma unroll 1
        for (int n0 = 0; n0 < 128; n0 += 32) {   // 4 n-blocks in flight
            float acc[4][4];
#pragma unroll
            for (int jj = 0; jj < 4; jj++)
#pragma unroll
                for (int s = 0; s < 4; s++) acc[jj][s] = 0.f;

#pragma unroll
            for (int kc = 0; kc < 16; kc++) {
                const float2* wrow = sWp + (kc * 4 + q) * 132 + n0 + p;
#pragma unroll
                for (int jj = 0; jj < 4; jj++) {
                    float2 bb = wrow[jj * 8];
                    mma_tf32(acc[jj], A[kc], __float_as_uint(bb.x),
                             __float_as_uint(bb.y));
                }
            }

#pragma unroll
            for (int jj = 0; jj < 4; jj++) {
                const int col = n0 + jj * 8 + q * 2;
                if (g0) *(float2*)(job.Y + (size_t)r0 * C128 + col) =
                            make_float2(acc[jj][0], acc[jj][1]);
                if (g1) *(float2*)(job.Y + (size_t)(r0 + 8) * C128 + col) =
                            make_float2(acc[jj][2], acc[jj][3]);
            }
        }
    }
}

// ---------------------------------------------------------------------------
// COO SPMM scatter: O[rows[e]] += vals[e] * Y[cols[e]]  (warp per nnz)
// ---------------------------------------------------------------------------
__global__ void __launch_bounds__(256) spmm_acc(const int* __restrict__ rows,
                                                const int* __restrict__ cols,
                                                const float* __restrict__ vals,
                                                int nnz,
                                                const float* __restrict__ Y,
                                                float* __restrict__ O) {
    int gthr = blockIdx.x * blockDim.x + threadIdx.x;
    int e = gthr >> 5;
    if (e >= nnz) return;
    int lane = gthr & 31;
    int r = __ldg(rows + e);
    int c = __ldg(cols + e);
    float v = __ldg(vals + e);
    float4 a = *(const float4*)(Y + (size_t)c * C128 + lane * 4);
    a.x *= v; a.y *= v; a.z *= v; a.w *= v;
    float* dst = O + (size_t)r * C128 + lane * 4;
    asm volatile("red.global.add.v4.f32 [%0], {%1, %2, %3, %4};"
                 :: "l"(dst), "f"(a.x), "f"(a.y), "f"(a.z), "f"(a.w)
                 : "memory");
}

// ---------------------------------------------------------------------------
// Head: out = softmax(sigmoid(M0) @ Wout + b). One warp per row.
// ---------------------------------------------------------------------------
__global__ void __launch_bounds__(256) head_k(const float* __restrict__ X,
                                              const float* __restrict__ Wout,
                                              const float* __restrict__ bout,
                                              float* __restrict__ out, int M) {
    __shared__ float sW[128 * 10];
    __shared__ float sb[10];
    int t = threadIdx.x;
    for (int i = t; i < 1280; i += blockDim.x) sW[i] = Wout[i];
    if (t < 10) sb[t] = bout[t];
    __syncthreads();

    int warp = (blockIdx.x * blockDim.x + t) >> 5;
    int lane = t & 31;
    if (warp >= M) return;

    const float* xr = X + (size_t)warp * C128;
    float acc[10];
#pragma unroll
    for (int j = 0; j < 10; j++) acc[j] = 0.f;
#pragma unroll
    for (int i = 0; i < 4; i++) {
        int k = lane + 32 * i;
        float xv = __ldg(xr + k);
        xv = 1.f / (1.f + __expf(-xv));   // fused sigmoid
#pragma unroll
        for (int j = 0; j < 10; j++) acc[j] = fmaf(xv, sW[k * 10 + j], acc[j]);
    }
#pragma unroll
    for (int j = 0; j < 10; j++) {
#pragma unroll
        for (int o = 16; o > 0; o >>= 1)
            acc[j] += __shfl_down_sync(0xffffffffu, acc[j], o);
    }
    if (lane == 0) {
        float mx = -1e30f;
#pragma unroll
        for (int j = 0; j < 10; j++) { acc[j] += sb[j]; mx = fmaxf(mx, acc[j]); }
        float s = 0.f;
#pragma unroll
        for (int j = 0; j < 10; j++) { acc[j] = __expf(acc[j] - mx); s += acc[j]; }
        float inv = 1.f / s;
#pragma unroll
        for (int j = 0; j < 10; j++) out[(size_t)warp * 10 + j] = acc[j] * inv;
    }
}

// ---------------------------------------------------------------------------
// Host orchestration
// ---------------------------------------------------------------------------
extern "C" void kernel_launch(void* const* d_in, const int* in_sizes, int n_in,
                              void* d_out, int out_size) {
    const int N[4]      = {N0, N1, N2, N3};
    const int ROWOFF[4] = {0, 40000, 160000, 240000};
    const int ADJNNZ[4] = {320000, 960000, 640000, 160000};
    const int INCNNZ[3] = {240000, 240000, 80000};

    const int SAME_OFF[4] = {0, 40000, 160000, 240000};
    const int H2L_OFF[3]  = {260000, 380000, 460000};  // rank r h2l (from x_{r+1})
    const int L2H_OFF[3]  = {480000, 520000, 640000};  // rank r+1 l2h (from x_r)

    const float* x_in[4] = {(const float*)d_in[0], (const float*)d_in[1],
                            (const float*)d_in[2], (const float*)d_in[3]};
    const int*   adj_row[4]; const int* adj_col[4]; const float* adj_val[4];
    for (int r = 0; r < 4; r++) {
        adj_row[r] = (const int*)d_in[4 + 3 * r];
        adj_col[r] = (const int*)d_in[5 + 3 * r];
        adj_val[r] = (const float*)d_in[6 + 3 * r];
    }
    const int* inc_row[3]; const int* inc_col[3]; const float* inc_val[3];
    for (int i = 0; i < 3; i++) {
        inc_row[i] = (const int*)d_in[16 + 3 * i];
        inc_col[i] = (const int*)d_in[17 + 3 * i];
        inc_val[i] = (const float*)d_in[18 + 3 * i];
    }
    const float* W_same = (const float*)d_in[25];
    const float* W_h2l  = (const float*)d_in[26];
    const float* W_l2h  = (const float*)d_in[27];
    const float* W_out  = (const float*)d_in[28];
    const float* b_out  = (const float*)d_in[29];
    float* out = (float*)d_out;

    float *gm, *gy;
    cudaGetSymbolAddress((void**)&gm, g_m);
    cudaGetSymbolAddress((void**)&gy, g_y);

    const int GSMEM = WCHUNK * (int)sizeof(float2);  // 67584 B
    cudaFuncSetAttribute(gemm_all, cudaFuncAttributeMaxDynamicSharedMemorySize,
                         GSMEM);

    const int WMAT = 128 * 128;

    for (int l = 0; l < 2; l++) {
        const float* xs[4];
        int sig = (l == 0) ? 0 : 1;  // layer-2 inputs are sigmoid(g_m)
        for (int r = 0; r < 4; r++)
            xs[r] = (l == 0) ? x_in[r] : (gm + (size_t)ROWOFF[r] * C128);

        // phase A: build job table (10 GEMMs), single fused launch
        GemmJobs P;
        P.sig = sig;
        int nj = 0, tot = 0;
        auto add = [&](const float* X, const float* W, float* Y, int M) {
            P.j[nj].X = X; P.j[nj].W = W; P.j[nj].Y = Y; P.j[nj].M = M;
            P.j[nj].tile0 = tot;
            tot += (M + 127) / 128;
            nj++;
        };
        for (int r = 0; r < 4; r++)
            add(xs[r], W_same + (size_t)(l * 4 + r) * WMAT,
                gy + (size_t)SAME_OFF[r] * C128, N[r]);
        for (int r = 0; r < 3; r++)   // h2l for rank r uses x_{r+1}
            add(xs[r + 1], W_h2l + (size_t)(l * 3 + r) * WMAT,
                gy + (size_t)H2L_OFF[r] * C128, N[r + 1]);
        for (int r = 1; r < 4; r++)   // l2h for rank r uses x_{r-1}
            add(xs[r - 1], W_l2h + (size_t)(l * 3 + (r - 1)) * WMAT,
                gy + (size_t)L2H_OFF[r - 1] * C128, N[r - 1]);
        P.njobs = nj;
        P.tot = tot;

        int grid = tot < 296 ? tot : 296;   // 2 CTAs/SM
        gemm_all<<<grid, 256, GSMEM>>>(P);

        // phase B: zero accumulator (GEMMs above already consumed g_m)
        cudaMemsetAsync(gm, 0, (size_t)NTOT * C128 * sizeof(float));

        // phase C: scatter-add SPMMs
        for (int r = 0; r < 4; r++) {
            int blocks = (ADJNNZ[r] * 32 + 255) / 256;
            spmm_acc<<<blocks, 256>>>(adj_row[r], adj_col[r], adj_val[r],
                                      ADJNNZ[r],
                                      gy + (size_t)SAME_OFF[r] * C128,
                                      gm + (size_t)ROWOFF[r] * C128);
        }
        for (int r = 0; r < 3; r++) {
            int blocks = (INCNNZ[r] * 32 + 255) / 256;
            spmm_acc<<<blocks, 256>>>(inc_row[r], inc_col[r], inc_val[r],
                                      INCNNZ[r],
                                      gy + (size_t)H2L_OFF[r] * C128,
                                      gm + (size_t)ROWOFF[r] * C128);
        }
        for (int r = 1; r < 4; r++) {
            int i = r - 1;
            int blocks = (INCNNZ[i] * 32 + 255) / 256;
            spmm_acc<<<blocks, 256>>>(inc_col[i], inc_row[i], inc_val[i],
                                      INCNNZ[i],
                                      gy + (size_t)L2H_OFF[i] * C128,
                                      gm + (size_t)ROWOFF[r] * C128);
        }
    }

    // head: softmax(sigmoid(m0) @ W_out + b_out)
    int blocks = (N0 * 32 + 255) / 256;
    head_k<<<blocks, 256>>>(gm, W_out, b_out, out, N0);
}

// round 16
// speedup vs baseline: 1.8101x; 1.1853x over previous
#include <cuda_runtime.h>
#include <cuda_bf16.h>
#include <cstdint>

// ---------------------------------------------------------------------------
// SCCN forward: 4 ranks, C=128, L=2 layers, sigmoid update, softmax head.
// R15: SPMM scatter-atomics replaced by CSR gather. CSR for all 10 sparse
//      operators built on-device once per call (layer-invariant), then each
//      layer's aggregation is ONE warp-per-dest-row gather kernel writing
//      every g_m row exactly once (no atomics, no memset).
// GEMM phase unchanged from R14 (single fused persistent mma launch/layer).
// ---------------------------------------------------------------------------

#define C128 128

static const int N0 = 40000, N1 = 120000, N2 = 80000, N3 = 20000;
static const int NTOT = 260000;
static const int YROWS = 720000;

#define ETOT 3200000        // total edges across all 10 structures
#define RTOT 720000         // total rows across all 10 structures
#define NTILES 704          // ceil(RTOT / 1024)

__device__ float g_m[(size_t)NTOT * C128];
__device__ float g_y[(size_t)YROWS * C128];

// CSR scratch
__device__ int   g_cnt[RTOT];
__device__ int   g_cursor[RTOT];
__device__ int   g_start[RTOT + 1];
__device__ int   g_tile[NTILES];
__device__ int   g_ecol[ETOT];
__device__ float g_eval[ETOT];

// ------------------------- PTX helpers -------------------------------------
__device__ __forceinline__ uint32_t f2tf32(float f) {
    uint32_t r;
    asm("cvt.rna.tf32.f32 %0, %1;" : "=r"(r) : "f"(f));
    return r;
}
__device__ __forceinline__ void mma_tf32(float* c, const uint32_t* a,
                                         uint32_t b0, uint32_t b1) {
    asm volatile(
        "mma.sync.aligned.m16n8k8.row.col.f32.tf32.tf32.f32 "
        "{%0,%1,%2,%3}, {%4,%5,%6,%7}, {%8,%9}, {%0,%1,%2,%3};"
        : "+f"(c[0]), "+f"(c[1]), "+f"(c[2]), "+f"(c[3])
        : "r"(a[0]), "r"(a[1]), "r"(a[2]), "r"(a[3]), "r"(b0), "r"(b1));
}

// ===========================================================================
// CSR build (once per call)
// ===========================================================================
struct Segs {
    const int* key[10];    // dest-row index array per structure
    const int* other[10];  // source index array
    const float* val[10];
    int ebase[11];         // edge-space segment starts (+ total)
    int rbase[10];         // row-space base per structure
};

__global__ void __launch_bounds__(256) hist_k(Segs S, int* __restrict__ cnt) {
    int e = blockIdx.x * blockDim.x + threadIdx.x;
    if (e >= ETOT) return;
    int s = 0;
#pragma unroll
    for (int i = 1; i < 10; i++) if (e >= S.ebase[i]) s = i;
    int le = e - S.ebase[s];
    atomicAdd(&cnt[S.rbase[s] + __ldg(S.key[s] + le)], 1);
}

__global__ void __launch_bounds__(256) scan1(const int* __restrict__ cnt,
                                             int* __restrict__ tile) {
    __shared__ int sh[256];
    int base = blockIdx.x * 1024, t = threadIdx.x;
    int s = 0;
#pragma unroll
    for (int i = 0; i < 4; i++) {
        int idx = base + t * 4 + i;
        s += (idx < RTOT) ? cnt[idx] : 0;
    }
    sh[t] = s;
    __syncthreads();
    for (int o = 128; o > 0; o >>= 1) {
        if (t < o) sh[t] += sh[t + o];
        __syncthreads();
    }
    if (t == 0) tile[blockIdx.x] = sh[0];
}

__global__ void __launch_bounds__(1024) scan2(int* __restrict__ tile) {
    __shared__ int sh[1024];
    int t = threadIdx.x;
    int mine = (t < NTILES) ? tile[t] : 0;
    sh[t] = mine;
    __syncthreads();
    for (int o = 1; o < 1024; o <<= 1) {
        int v = (t >= o) ? sh[t - o] : 0;
        __syncthreads();
        sh[t] += v;
        __syncthreads();
    }
    if (t < NTILES) tile[t] = sh[t] - mine;   // exclusive
    if (t == 0) { /* nothing */ }
}

__global__ void __launch_bounds__(256) scan3(const int* __restrict__ cnt,
                                             const int* __restrict__ tile,
                                             int* __restrict__ start) {
    __shared__ int sh[256];
    int base = blockIdx.x * 1024, t = threadIdx.x;
    int v[4], s = 0;
#pragma unroll
    for (int i = 0; i < 4; i++) {
        int idx = base + t * 4 + i;
        v[i] = (idx < RTOT) ? cnt[idx] : 0;
        s += v[i];
    }
    int mine = s;
    sh[t] = s;
    __syncthreads();
    for (int o = 1; o < 256; o <<= 1) {
        int u = (t >= o) ? sh[t - o] : 0;
        __syncthreads();
        sh[t] += u;
        __syncthreads();
    }
    int exc = sh[t] - mine + tile[blockIdx.x];
#pragma unroll
    for (int i = 0; i < 4; i++) {
        int idx = base + t * 4 + i;
        if (idx < RTOT) start[idx] = exc;
        exc += v[i];
    }
    if (blockIdx.x == 0 && t == 0) start[RTOT] = ETOT;
}

__global__ void __launch_bounds__(256) scatter_k(Segs S,
                                                 const int* __restrict__ start,
                                                 int* __restrict__ cursor,
                                                 int* __restrict__ ecol,
                                                 float* __restrict__ eval) {
    int e = blockIdx.x * blockDim.x + threadIdx.x;
    if (e >= ETOT) return;
    int s = 0;
#pragma unroll
    for (int i = 1; i < 10; i++) if (e >= S.ebase[i]) s = i;
    int le = e - S.ebase[s];
    int row = S.rbase[s] + __ldg(S.key[s] + le);
    int pos = __ldg(start + row) + atomicAdd(&cursor[row], 1);
    ecol[pos] = __ldg(S.other[s] + le);
    eval[pos] = __ldg(S.val[s] + le);
}

// ===========================================================================
// SPMM gather: one warp per destination row, 2-3 CSR lists fused, no atomics.
// ===========================================================================
__device__ __forceinline__ void accum_list(const int* __restrict__ start,
                                           int row,
                                           const int* __restrict__ ecol,
                                           const float* __restrict__ eval,
                                           const float* __restrict__ Y,
                                           int lane, float4& acc) {
    int s = __ldg(start + row), e = __ldg(start + row + 1);
    for (int b = s; b < e; b += 32) {
        int n = min(32, e - b);
        int col = 0;
        float v = 0.f;
        if (lane < n) { col = __ldg(ecol + b + lane); v = __ldg(eval + b + lane); }
        for (int j = 0; j < n; j++) {
            int c = __shfl_sync(0xffffffffu, col, j);
            float vv = __shfl_sync(0xffffffffu, v, j);
            float4 y = *(const float4*)(Y + (size_t)c * C128 + lane * 4);
            acc.x = fmaf(vv, y.x, acc.x);
            acc.y = fmaf(vv, y.y, acc.y);
            acc.z = fmaf(vv, y.z, acc.z);
            acc.w = fmaf(vv, y.w, acc.w);
        }
    }
}

__global__ void __launch_bounds__(256) spmm_gather(
    const int* __restrict__ start, const int* __restrict__ ecol,
    const float* __restrict__ eval, const float* __restrict__ gy,
    float* __restrict__ gm) {
    int w = (blockIdx.x * blockDim.x + threadIdx.x) >> 5;
    if (w >= NTOT) return;
    int lane = threadIdx.x & 31;

    // rank resolution (dest row spaces: 0..40k..160k..240k..260k)
    int r, lr;
    if (w < 40000)       { r = 0; lr = w; }
    else if (w < 160000) { r = 1; lr = w - 40000; }
    else if (w < 240000) { r = 2; lr = w - 160000; }
    else                 { r = 3; lr = w - 240000; }

    // g_y projection row offsets
    const int SAME_OFF[4] = {0, 40000, 160000, 240000};
    const int H2L_OFF[3]  = {260000, 380000, 460000};
    const int L2H_OFF[3]  = {480000, 520000, 640000};
    // CSR concat row bases
    const int HBASE[3] = {260000, 300000, 420000};
    const int LBASE[3] = {500000, 620000, 700000};

    float4 acc = make_float4(0.f, 0.f, 0.f, 0.f);
    // adjacency (CSR rows coincide with global dest index w)
    accum_list(start, w, ecol, eval,
               gy + (size_t)SAME_OFF[r] * C128, lane, acc);
    if (r < 3)
        accum_list(start, HBASE[r] + lr, ecol, eval,
                   gy + (size_t)H2L_OFF[r] * C128, lane, acc);
    if (r > 0)
        accum_list(start, LBASE[r - 1] + lr, ecol, eval,
                   gy + (size_t)L2H_OFF[r - 1] * C128, lane, acc);

    *(float4*)(gm + (size_t)w * C128 + lane * 4) = acc;
}

// ===========================================================================
// Fused GEMM phase (unchanged from R14)
// ===========================================================================
#define WCHUNK (64 * 132)

struct GemmJob {
    const float* X;
    const float* W;
    float* Y;
    int M;
    int tile0;
};
struct GemmJobs {
    GemmJob j[10];
    int njobs;
    int tot;
    int sig;
};

__global__ void __launch_bounds__(256, 2) gemm_all(GemmJobs P) {
    extern __shared__ __align__(16) float2 sWp[];
    const int t = threadIdx.x;
    const int lane = t & 31, wid = t >> 5;
    const int q = lane & 3, p = lane >> 2;

    const int per = (P.tot + gridDim.x - 1) / gridDim.x;
    const int c0 = blockIdx.x * per;
    const int c1 = min(c0 + per, P.tot);
    if (c0 >= c1) return;

    int cur = -1;
    for (int tt = c0; tt < c1; tt++) {
        int j = (cur < 0) ? 0 : cur;
        while (j + 1 < P.njobs && tt >= P.j[j + 1].tile0) j++;
        if (j != cur) {
            __syncthreads();
            const float* W = P.j[j].W;
            for (int i = t; i < 8192; i += 256) {
                int kcq = i >> 7, n = i & 127;
                int k_lo = (kcq >> 2) * 8 + (kcq & 3);
                float2 v;
                v.x = __uint_as_float(f2tf32(__ldg(W + k_lo * C128 + n)));
                v.y = __uint_as_float(f2tf32(__ldg(W + (k_lo + 4) * C128 + n)));
                sWp[kcq * 132 + n] = v;
            }
            __syncthreads();
            cur = j;
        }
        const GemmJob& job = P.j[j];
        const int M = job.M;
        const int tile = tt - job.tile0;
        const int r0 = (tile << 7) + (wid << 4) + p;
        const bool g0 = r0 < M, g1 = (r0 + 8) < M;

        uint32_t A[16][4];
        {
            const float* x0 = job.X + (size_t)r0 * C128 + q;
            const float* x1 = x0 + 8 * C128;
#pragma unroll
            for (int kc = 0; kc < 16; kc++) {
                int col = kc * 8;
                float v0 = g0 ? __ldg(x0 + col)     : 0.f;
                float v1 = g1 ? __ldg(x1 + col)     : 0.f;
                float v2 = g0 ? __ldg(x0 + col + 4) : 0.f;
                float v3 = g1 ? __ldg(x1 + col + 4) : 0.f;
                if (P.sig) {
                    v0 = 1.f / (1.f + __expf(-v0));
                    v1 = 1.f / (1.f + __expf(-v1));
                    v2 = 1.f / (1.f + __expf(-v2));
                    v3 = 1.f / (1.f + __expf(-v3));
                }
                A[kc][0] = f2tf32(v0);
                A[kc][1] = f2tf32(v1);
                A[kc][2] = f2tf32(v2);
                A[kc][3] = f2tf32(v3);
            }
        }

#pragma unroll 1
        for (int n0 = 0; n0 < 128; n0 += 32) {
            float acc[4][4];
#pragma unroll
            for (int jj = 0; jj < 4; jj++)
#pragma unroll
                for (int s = 0; s < 4; s++) acc[jj][s] = 0.f;

#pragma unroll
            for (int kc = 0; kc < 16; kc++) {
                const float2* wrow = sWp + (kc * 4 + q) * 132 + n0 + p;
#pragma unroll
                for (int jj = 0; jj < 4; jj++) {
                    float2 bb = wrow[jj * 8];
                    mma_tf32(acc[jj], A[kc], __float_as_uint(bb.x),
                             __float_as_uint(bb.y));
                }
            }

#pragma unroll
            for (int jj = 0; jj < 4; jj++) {
                const int col = n0 + jj * 8 + q * 2;
                if (g0) *(float2*)(job.Y + (size_t)r0 * C128 + col) =
                            make_float2(acc[jj][0], acc[jj][1]);
                if (g1) *(float2*)(job.Y + (size_t)(r0 + 8) * C128 + col) =
                            make_float2(acc[jj][2], acc[jj][3]);
            }
        }
    }
}

// ---------------------------------------------------------------------------
// Head: out = softmax(sigmoid(M0) @ Wout + b). One warp per row.
// ---------------------------------------------------------------------------
__global__ void __launch_bounds__(256) head_k(const float* __restrict__ X,
                                              const float* __restrict__ Wout,
                                              const float* __restrict__ bout,
                                              float* __restrict__ out, int M) {
    __shared__ float sW[128 * 10];
    __shared__ float sb[10];
    int t = threadIdx.x;
    for (int i = t; i < 1280; i += blockDim.x) sW[i] = Wout[i];
    if (t < 10) sb[t] = bout[t];
    __syncthreads();

    int warp = (blockIdx.x * blockDim.x + t) >> 5;
    int lane = t & 31;
    if (warp >= M) return;

    const float* xr = X + (size_t)warp * C128;
    float acc[10];
#pragma unroll
    for (int j = 0; j < 10; j++) acc[j] = 0.f;
#pragma unroll
    for (int i = 0; i < 4; i++) {
        int k = lane + 32 * i;
        float xv = __ldg(xr + k);
        xv = 1.f / (1.f + __expf(-xv));
#pragma unroll
        for (int j = 0; j < 10; j++) acc[j] = fmaf(xv, sW[k * 10 + j], acc[j]);
    }
#pragma unroll
    for (int j = 0; j < 10; j++) {
#pragma unroll
        for (int o = 16; o > 0; o >>= 1)
            acc[j] += __shfl_down_sync(0xffffffffu, acc[j], o);
    }
    if (lane == 0) {
        float mx = -1e30f;
#pragma unroll
        for (int j = 0; j < 10; j++) { acc[j] += sb[j]; mx = fmaxf(mx, acc[j]); }
        float s = 0.f;
#pragma unroll
        for (int j = 0; j < 10; j++) { acc[j] = __expf(acc[j] - mx); s += acc[j]; }
        float inv = 1.f / s;
#pragma unroll
        for (int j = 0; j < 10; j++) out[(size_t)warp * 10 + j] = acc[j] * inv;
    }
}

// ---------------------------------------------------------------------------
// Host orchestration
// ---------------------------------------------------------------------------
extern "C" void kernel_launch(void* const* d_in, const int* in_sizes, int n_in,
                              void* d_out, int out_size) {
    const int N[4]      = {N0, N1, N2, N3};
    const int ROWOFF[4] = {0, 40000, 160000, 240000};

    const int SAME_OFF[4] = {0, 40000, 160000, 240000};
    const int H2L_OFF[3]  = {260000, 380000, 460000};
    const int L2H_OFF[3]  = {480000, 520000, 640000};

    const float* x_in[4] = {(const float*)d_in[0], (const float*)d_in[1],
                            (const float*)d_in[2], (const float*)d_in[3]};
    const int*   adj_row[4]; const int* adj_col[4]; const float* adj_val[4];
    for (int r = 0; r < 4; r++) {
        adj_row[r] = (const int*)d_in[4 + 3 * r];
        adj_col[r] = (const int*)d_in[5 + 3 * r];
        adj_val[r] = (const float*)d_in[6 + 3 * r];
    }
    const int* inc_row[3]; const int* inc_col[3]; const float* inc_val[3];
    for (int i = 0; i < 3; i++) {
        inc_row[i] = (const int*)d_in[16 + 3 * i];
        inc_col[i] = (const int*)d_in[17 + 3 * i];
        inc_val[i] = (const float*)d_in[18 + 3 * i];
    }
    const float* W_same = (const float*)d_in[25];
    const float* W_h2l  = (const float*)d_in[26];
    const float* W_l2h  = (const float*)d_in[27];
    const float* W_out  = (const float*)d_in[28];
    const float* b_out  = (const float*)d_in[29];
    float* out = (float*)d_out;

    float *gm, *gy;
    int *cnt, *cursor, *startp, *tilep, *ecol;
    float* eval;
    cudaGetSymbolAddress((void**)&gm, g_m);
    cudaGetSymbolAddress((void**)&gy, g_y);
    cudaGetSymbolAddress((void**)&cnt, g_cnt);
    cudaGetSymbolAddress((void**)&cursor, g_cursor);
    cudaGetSymbolAddress((void**)&startp, g_start);
    cudaGetSymbolAddress((void**)&tilep, g_tile);
    cudaGetSymbolAddress((void**)&ecol, g_ecol);
    cudaGetSymbolAddress((void**)&eval, g_eval);

    // ---------------- CSR build (once; graph structure is layer-invariant) --
    Segs S;
    {
        const int ADJNNZ[4] = {320000, 960000, 640000, 160000};
        const int INCNNZ[3] = {240000, 240000, 80000};
        int eb = 0, k = 0;
        // A0..A3: key=adj_row, other=adj_col, rbase=ROWOFF
        for (int r = 0; r < 4; r++, k++) {
            S.key[k] = adj_row[r]; S.other[k] = adj_col[r]; S.val[k] = adj_val[r];
            S.ebase[k] = eb; S.rbase[k] = ROWOFF[r];
            eb += ADJNNZ[r];
        }
        // H1..H3 (h2l into rank r): key=inc_{r+1}_row, other=inc_{r+1}_col
        const int HBASE[3] = {260000, 300000, 420000};
        for (int i = 0; i < 3; i++, k++) {
            S.key[k] = inc_row[i]; S.other[k] = inc_col[i]; S.val[k] = inc_val[i];
            S.ebase[k] = eb; S.rbase[k] = HBASE[i];
            eb += INCNNZ[i];
        }
        // L1..L3 (l2h into rank r+1): key=inc_col, other=inc_row
        const int LBASE[3] = {500000, 620000, 700000};
        for (int i = 0; i < 3; i++, k++) {
            S.key[k] = inc_col[i]; S.other[k] = inc_row[i]; S.val[k] = inc_val[i];
            S.ebase[k] = eb; S.rbase[k] = LBASE[i];
            eb += INCNNZ[i];
        }
        S.ebase[10] = eb;  // == ETOT
    }
    cudaMemsetAsync(cnt, 0, RTOT * sizeof(int));
    cudaMemsetAsync(cursor, 0, RTOT * sizeof(int));
    {
        int blocks = (ETOT + 255) / 256;
        hist_k<<<blocks, 256>>>(S, cnt);
        scan1<<<NTILES, 256>>>(cnt, tilep);
        scan2<<<1, 1024>>>(tilep);
        scan3<<<NTILES, 256>>>(cnt, tilep, startp);
        scatter_k<<<blocks, 256>>>(S, startp, cursor, ecol, eval);
    }

    // ---------------- layers -----------------------------------------------
    const int GSMEM = WCHUNK * (int)sizeof(float2);  // 67584 B
    cudaFuncSetAttribute(gemm_all, cudaFuncAttributeMaxDynamicSharedMemorySize,
                         GSMEM);
    const int WMAT = 128 * 128;

    for (int l = 0; l < 2; l++) {
        const float* xs[4];
        int sig = (l == 0) ? 0 : 1;
        for (int r = 0; r < 4; r++)
            xs[r] = (l == 0) ? x_in[r] : (gm + (size_t)ROWOFF[r] * C128);

        GemmJobs P;
        P.sig = sig;
        int nj = 0, tot = 0;
        auto add = [&](const float* X, const float* W, float* Y, int M) {
            P.j[nj].X = X; P.j[nj].W = W; P.j[nj].Y = Y; P.j[nj].M = M;
            P.j[nj].tile0 = tot;
            tot += (M + 127) / 128;
            nj++;
        };
        for (int r = 0; r < 4; r++)
            add(xs[r], W_same + (size_t)(l * 4 + r) * WMAT,
                gy + (size_t)SAME_OFF[r] * C128, N[r]);
        for (int r = 0; r < 3; r++)
            add(xs[r + 1], W_h2l + (size_t)(l * 3 + r) * WMAT,
                gy + (size_t)H2L_OFF[r] * C128, N[r + 1]);
        for (int r = 1; r < 4; r++)
            add(xs[r - 1], W_l2h + (size_t)(l * 3 + (r - 1)) * WMAT,
                gy + (size_t)L2H_OFF[r - 1] * C128, N[r - 1]);
        P.njobs = nj;
        P.tot = tot;

        int grid = tot < 296 ? tot : 296;
        gemm_all<<<grid, 256, GSMEM>>>(P);

        // aggregation: one gather launch, writes all of g_m (no memset)
        int gblocks = (NTOT * 32 + 255) / 256;
        spmm_gather<<<gblocks, 256>>>(startp, ecol, eval, gy, gm);
    }

    // head: softmax(sigmoid(m0) @ W_out + b_out)
    int blocks = (N0 * 32 + 255) / 256;
    head_k<<<blocks, 256>>>(gm, W_out, b_out, out, N0);
}

// round 17
// speedup vs baseline: 4.4950x; 2.4833x over previous
#include <cuda_runtime.h>
#include <cuda_bf16.h>
#include <cstdint>

// ---------------------------------------------------------------------------
// SCCN forward: 4 ranks, C=128, L=2 layers, sigmoid update, softmax head.
// R17: dead-dataflow elimination. Output depends only on layer-2 rank 0, so:
//   layer 1 computes ranks {0,1} only  (5 GEMMs / 400k rows, 2.0M edges)
//   layer 2 computes rank 0 only       (2 GEMMs / 160k rows, 560k edges)
// CSR built once for the 5 live sparse operators. Kernel bodies = R16.
// ---------------------------------------------------------------------------

#define C128 128

static const int N0 = 40000, N1 = 120000, N2 = 80000, N3 = 20000;

#define ETOT 2000000        // live edges: adj0+adj1+inc1(h2l)+inc1(l2h)+inc2(h2l)
#define RTOT 440000         // CSR row space: 40k+120k+40k+120k+120k
#define NTILES 430          // ceil(RTOT / 1024)
#define YROWS 400000        // layer-1 projection rows
#define MROWS 200000        // m rows: L1 ranks {0,1} = 160k, L2 rank0 at 160k

__device__ float g_m[(size_t)MROWS * C128];
__device__ float g_y[(size_t)YROWS * C128];

// CSR scratch
__device__ int   g_cnt[RTOT];
__device__ int   g_cursor[RTOT];
__device__ int   g_start[RTOT + 1];
__device__ int   g_tile[NTILES];
__device__ int   g_ecol[ETOT];
__device__ float g_eval[ETOT];

// CSR row bases
#define RB_ADJ0   0        // 40k rows  (dest rank0)
#define RB_ADJ1   40000    // 120k rows (dest rank1)
#define RB_H2L0   160000   // 40k rows  (inc1 by row, dest rank0)
#define RB_L2H0   200000   // 120k rows (inc1 by col, dest rank1)
#define RB_H2L1   320000   // 120k rows (inc2 by row, dest rank1)

// g_y row offsets (layer 1)
#define Y_SAME0   0        // x0 @ Wsame[0][0] : 40k
#define Y_SAME1   40000    // x1 @ Wsame[0][1] : 120k
#define Y_H2L0    160000   // x1 @ Wh2l[0][0]  : 120k
#define Y_L2H0    280000   // x0 @ Wl2h[0][0]  : 40k
#define Y_H2L1    320000   // x2 @ Wh2l[0][1]  : 80k
// layer 2 reuses: Y2_SAME0 = 0 (40k), Y2_H2L0 = 40000 (120k)

// ------------------------- PTX helpers -------------------------------------
__device__ __forceinline__ uint32_t f2tf32(float f) {
    uint32_t r;
    asm("cvt.rna.tf32.f32 %0, %1;" : "=r"(r) : "f"(f));
    return r;
}
__device__ __forceinline__ void mma_tf32(float* c, const uint32_t* a,
                                         uint32_t b0, uint32_t b1) {
    asm volatile(
        "mma.sync.aligned.m16n8k8.row.col.f32.tf32.tf32.f32 "
        "{%0,%1,%2,%3}, {%4,%5,%6,%7}, {%8,%9}, {%0,%1,%2,%3};"
        : "+f"(c[0]), "+f"(c[1]), "+f"(c[2]), "+f"(c[3])
        : "r"(a[0]), "r"(a[1]), "r"(a[2]), "r"(a[3]), "r"(b0), "r"(b1));
}

// ===========================================================================
// CSR build (once per call) — 5 live structures
// ===========================================================================
struct Segs {
    const int* key[5];
    const int* other[5];
    const float* val[5];
    int ebase[6];
    int rbase[5];
};

__global__ void __launch_bounds__(256) hist_k(Segs S, int* __restrict__ cnt) {
    int e = blockIdx.x * blockDim.x + threadIdx.x;
    if (e >= ETOT) return;
    int s = 0;
#pragma unroll
    for (int i = 1; i < 5; i++) if (e >= S.ebase[i]) s = i;
    int le = e - S.ebase[s];
    atomicAdd(&cnt[S.rbase[s] + __ldg(S.key[s] + le)], 1);
}

__global__ void __launch_bounds__(256) scan1(const int* __restrict__ cnt,
                                             int* __restrict__ tile) {
    __shared__ int sh[256];
    int base = blockIdx.x * 1024, t = threadIdx.x;
    int s = 0;
#pragma unroll
    for (int i = 0; i < 4; i++) {
        int idx = base + t * 4 + i;
        s += (idx < RTOT) ? cnt[idx] : 0;
    }
    sh[t] = s;
    __syncthreads();
    for (int o = 128; o > 0; o >>= 1) {
        if (t < o) sh[t] += sh[t + o];
        __syncthreads();
    }
    if (t == 0) tile[blockIdx.x] = sh[0];
}

__global__ void __launch_bounds__(1024) scan2(int* __restrict__ tile) {
    __shared__ int sh[1024];
    int t = threadIdx.x;
    int mine = (t < NTILES) ? tile[t] : 0;
    sh[t] = mine;
    __syncthreads();
    for (int o = 1; o < 1024; o <<= 1) {
        int v = (t >= o) ? sh[t - o] : 0;
        __syncthreads();
        sh[t] += v;
        __syncthreads();
    }
    if (t < NTILES) tile[t] = sh[t] - mine;   // exclusive
}

__global__ void __launch_bounds__(256) scan3(const int* __restrict__ cnt,
                                             const int* __restrict__ tile,
                                             int* __restrict__ start) {
    __shared__ int sh[256];
    int base = blockIdx.x * 1024, t = threadIdx.x;
    int v[4], s = 0;
#pragma unroll
    for (int i = 0; i < 4; i++) {
        int idx = base + t * 4 + i;
        v[i] = (idx < RTOT) ? cnt[idx] : 0;
        s += v[i];
    }
    int mine = s;
    sh[t] = s;
    __syncthreads();
    for (int o = 1; o < 256; o <<= 1) {
        int u = (t >= o) ? sh[t - o] : 0;
        __syncthreads();
        sh[t] += u;
        __syncthreads();
    }
    int exc = sh[t] - mine + tile[blockIdx.x];
#pragma unroll
    for (int i = 0; i < 4; i++) {
        int idx = base + t * 4 + i;
        if (idx < RTOT) start[idx] = exc;
        exc += v[i];
    }
    if (blockIdx.x == 0 && t == 0) start[RTOT] = ETOT;
}

__global__ void __launch_bounds__(256) scatter_k(Segs S,
                                                 const int* __restrict__ start,
                                                 int* __restrict__ cursor,
                                                 int* __restrict__ ecol,
                                                 float* __restrict__ eval) {
    int e = blockIdx.x * blockDim.x + threadIdx.x;
    if (e >= ETOT) return;
    int s = 0;
#pragma unroll
    for (int i = 1; i < 5; i++) if (e >= S.ebase[i]) s = i;
    int le = e - S.ebase[s];
    int row = S.rbase[s] + __ldg(S.key[s] + le);
    int pos = __ldg(start + row) + atomicAdd(&cursor[row], 1);
    ecol[pos] = __ldg(S.other[s] + le);
    eval[pos] = __ldg(S.val[s] + le);
}

// ===========================================================================
// SPMM gather: one warp per destination row, CSR lists fused, no atomics.
// ===========================================================================
__device__ __forceinline__ void accum_list(const int* __restrict__ start,
                                           int row,
                                           const int* __restrict__ ecol,
                                           const float* __restrict__ eval,
                                           const float* __restrict__ Y,
                                           int lane, float4& acc) {
    int s = __ldg(start + row), e = __ldg(start + row + 1);
    for (int b = s; b < e; b += 32) {
        int n = min(32, e - b);
        int col = 0;
        float v = 0.f;
        if (lane < n) { col = __ldg(ecol + b + lane); v = __ldg(eval + b + lane); }
        for (int j = 0; j < n; j++) {
            int c = __shfl_sync(0xffffffffu, col, j);
            float vv = __shfl_sync(0xffffffffu, v, j);
            float4 y = *(const float4*)(Y + (size_t)c * C128 + lane * 4);
            acc.x = fmaf(vv, y.x, acc.x);
            acc.y = fmaf(vv, y.y, acc.y);
            acc.z = fmaf(vv, y.z, acc.z);
            acc.w = fmaf(vv, y.w, acc.w);
        }
    }
}

// Layer 1: dest rows 0..160k (rank0 40k, rank1 120k) -> g_m rows [0,160k)
__global__ void __launch_bounds__(256) gather_l1(
    const int* __restrict__ start, const int* __restrict__ ecol,
    const float* __restrict__ eval, const float* __restrict__ gy,
    float* __restrict__ gm) {
    int w = (blockIdx.x * blockDim.x + threadIdx.x) >> 5;
    if (w >= 160000) return;
    int lane = threadIdx.x & 31;

    float4 acc = make_float4(0.f, 0.f, 0.f, 0.f);
    if (w < 40000) {  // rank 0
        accum_list(start, RB_ADJ0 + w, ecol, eval,
                   gy + (size_t)Y_SAME0 * C128, lane, acc);
        accum_list(start, RB_H2L0 + w, ecol, eval,
                   gy + (size_t)Y_H2L0 * C128, lane, acc);
    } else {          // rank 1
        int lr = w - 40000;
        accum_list(start, RB_ADJ1 + lr, ecol, eval,
                   gy + (size_t)Y_SAME1 * C128, lane, acc);
        accum_list(start, RB_L2H0 + lr, ecol, eval,
                   gy + (size_t)Y_L2H0 * C128, lane, acc);
        accum_list(start, RB_H2L1 + lr, ecol, eval,
                   gy + (size_t)Y_H2L1 * C128, lane, acc);
    }
    *(float4*)(gm + (size_t)w * C128 + lane * 4) = acc;
}

// Layer 2: dest rows rank0 only -> g_m rows [160k, 200k)
__global__ void __launch_bounds__(256) gather_l2(
    const int* __restrict__ start, const int* __restrict__ ecol,
    const float* __restrict__ eval, const float* __restrict__ gy,
    float* __restrict__ gm) {
    int w = (blockIdx.x * blockDim.x + threadIdx.x) >> 5;
    if (w >= 40000) return;
    int lane = threadIdx.x & 31;

    float4 acc = make_float4(0.f, 0.f, 0.f, 0.f);
    accum_list(start, RB_ADJ0 + w, ecol, eval,
               gy + (size_t)0 * C128, lane, acc);        // y2_same0 @ 0
    accum_list(start, RB_H2L0 + w, ecol, eval,
               gy + (size_t)40000 * C128, lane, acc);    // y2_h2l0 @ 40000
    *(float4*)(gm + (size_t)(160000 + w) * C128 + lane * 4) = acc;
}

// ===========================================================================
// Fused GEMM phase (job table, persistent; body identical to R14/R16)
// ===========================================================================
#define WCHUNK (64 * 132)

struct GemmJob {
    const float* X;
    const float* W;
    float* Y;
    int M;
    int tile0;
};
struct GemmJobs {
    GemmJob j[5];
    int njobs;
    int tot;
    int sig;
};

__global__ void __launch_bounds__(256, 2) gemm_all(GemmJobs P) {
    extern __shared__ __align__(16) float2 sWp[];
    const int t = threadIdx.x;
    const int lane = t & 31, wid = t >> 5;
    const int q = lane & 3, p = lane >> 2;

    const int per = (P.tot + gridDim.x - 1) / gridDim.x;
    const int c0 = blockIdx.x * per;
    const int c1 = min(c0 + per, P.tot);
    if (c0 >= c1) return;

    int cur = -1;
    for (int tt = c0; tt < c1; tt++) {
        int j = (cur < 0) ? 0 : cur;
        while (j + 1 < P.njobs && tt >= P.j[j + 1].tile0) j++;
        if (j != cur) {
            __syncthreads();
            const float* W = P.j[j].W;
            for (int i = t; i < 8192; i += 256) {
                int kcq = i >> 7, n = i & 127;
                int k_lo = (kcq >> 2) * 8 + (kcq & 3);
                float2 v;
                v.x = __uint_as_float(f2tf32(__ldg(W + k_lo * C128 + n)));
                v.y = __uint_as_float(f2tf32(__ldg(W + (k_lo + 4) * C128 + n)));
                sWp[kcq * 132 + n] = v;
            }
            __syncthreads();
            cur = j;
        }
        const GemmJob& job = P.j[j];
        const int M = job.M;
        const int tile = tt - job.tile0;
        const int r0 = (tile << 7) + (wid << 4) + p;
        const bool g0 = r0 < M, g1 = (r0 + 8) < M;

        uint32_t A[16][4];
        {
            const float* x0 = job.X + (size_t)r0 * C128 + q;
            const float* x1 = x0 + 8 * C128;
#pragma unroll
            for (int kc = 0; kc < 16; kc++) {
                int col = kc * 8;
                float v0 = g0 ? __ldg(x0 + col)     : 0.f;
                float v1 = g1 ? __ldg(x1 + col)     : 0.f;
                float v2 = g0 ? __ldg(x0 + col + 4) : 0.f;
                float v3 = g1 ? __ldg(x1 + col + 4) : 0.f;
                if (P.sig) {
                    v0 = 1.f / (1.f + __expf(-v0));
                    v1 = 1.f / (1.f + __expf(-v1));
                    v2 = 1.f / (1.f + __expf(-v2));
                    v3 = 1.f / (1.f + __expf(-v3));
                }
                A[kc][0] = f2tf32(v0);
                A[kc][1] = f2tf32(v1);
                A[kc][2] = f2tf32(v2);
                A[kc][3] = f2tf32(v3);
            }
        }

#pragma unroll 1
        for (int n0 = 0; n0 < 128; n0 += 32) {
            float acc[4][4];
#pragma unroll
            for (int jj = 0; jj < 4; jj++)
#pragma unroll
                for (int s = 0; s < 4; s++) acc[jj][s] = 0.f;

#pragma unroll
            for (int kc = 0; kc < 16; kc++) {
                const float2* wrow = sWp + (kc * 4 + q) * 132 + n0 + p;
#pragma unroll
                for (int jj = 0; jj < 4; jj++) {
                    float2 bb = wrow[jj * 8];
                    mma_tf32(acc[jj], A[kc], __float_as_uint(bb.x),
                             __float_as_uint(bb.y));
                }
            }

#pragma unroll
            for (int jj = 0; jj < 4; jj++) {
                const int col = n0 + jj * 8 + q * 2;
                if (g0) *(float2*)(job.Y + (size_t)r0 * C128 + col) =
                            make_float2(acc[jj][0], acc[jj][1]);
                if (g1) *(float2*)(job.Y + (size_t)(r0 + 8) * C128 + col) =
                            make_float2(acc[jj][2], acc[jj][3]);
            }
        }
    }
}

// ---------------------------------------------------------------------------
// Head: out = softmax(sigmoid(M2) @ Wout + b). One warp per row.
// ---------------------------------------------------------------------------
__global__ void __launch_bounds__(256) head_k(const float* __restrict__ X,
                                              const float* __restrict__ Wout,
                                              const float* __restrict__ bout,
                                              float* __restrict__ out, int M) {
    __shared__ float sW[128 * 10];
    __shared__ float sb[10];
    int t = threadIdx.x;
    for (int i = t; i < 1280; i += blockDim.x) sW[i] = Wout[i];
    if (t < 10) sb[t] = bout[t];
    __syncthreads();

    int warp = (blockIdx.x * blockDim.x + t) >> 5;
    int lane = t & 31;
    if (warp >= M) return;

    const float* xr = X + (size_t)warp * C128;
    float acc[10];
#pragma unroll
    for (int j = 0; j < 10; j++) acc[j] = 0.f;
#pragma unroll
    for (int i = 0; i < 4; i++) {
        int k = lane + 32 * i;
        float xv = __ldg(xr + k);
        xv = 1.f / (1.f + __expf(-xv));
#pragma unroll
        for (int j = 0; j < 10; j++) acc[j] = fmaf(xv, sW[k * 10 + j], acc[j]);
    }
#pragma unroll
    for (int j = 0; j < 10; j++) {
#pragma unroll
        for (int o = 16; o > 0; o >>= 1)
            acc[j] += __shfl_down_sync(0xffffffffu, acc[j], o);
    }
    if (lane == 0) {
        float mx = -1e30f;
#pragma unroll
        for (int j = 0; j < 10; j++) { acc[j] += sb[j]; mx = fmaxf(mx, acc[j]); }
        float s = 0.f;
#pragma unroll
        for (int j = 0; j < 10; j++) { acc[j] = __expf(acc[j] - mx); s += acc[j]; }
        float inv = 1.f / s;
#pragma unroll
        for (int j = 0; j < 10; j++) out[(size_t)warp * 10 + j] = acc[j] * inv;
    }
}

// ---------------------------------------------------------------------------
// Host orchestration
// ---------------------------------------------------------------------------
extern "C" void kernel_launch(void* const* d_in, const int* in_sizes, int n_in,
                              void* d_out, int out_size) {
    const float* x_in[4] = {(const float*)d_in[0], (const float*)d_in[1],
                            (const float*)d_in[2], (const float*)d_in[3]};
    const int*   adj_row[4]; const int* adj_col[4]; const float* adj_val[4];
    for (int r = 0; r < 4; r++) {
        adj_row[r] = (const int*)d_in[4 + 3 * r];
        adj_col[r] = (const int*)d_in[5 + 3 * r];
        adj_val[r] = (const float*)d_in[6 + 3 * r];
    }
    const int* inc_row[3]; const int* inc_col[3]; const float* inc_val[3];
    for (int i = 0; i < 3; i++) {
        inc_row[i] = (const int*)d_in[16 + 3 * i];
        inc_col[i] = (const int*)d_in[17 + 3 * i];
        inc_val[i] = (const float*)d_in[18 + 3 * i];
    }
    const float* W_same = (const float*)d_in[25];  // (2,4,128,128)
    const float* W_h2l  = (const float*)d_in[26];  // (2,3,128,128)
    const float* W_l2h  = (const float*)d_in[27];  // (2,3,128,128)
    const float* W_out  = (const float*)d_in[28];
    const float* b_out  = (const float*)d_in[29];
    float* out = (float*)d_out;

    float *gm, *gy;
    int *cnt, *cursor, *startp, *tilep, *ecol;
    float* eval;
    cudaGetSymbolAddress((void**)&gm, g_m);
    cudaGetSymbolAddress((void**)&gy, g_y);
    cudaGetSymbolAddress((void**)&cnt, g_cnt);
    cudaGetSymbolAddress((void**)&cursor, g_cursor);
    cudaGetSymbolAddress((void**)&startp, g_start);
    cudaGetSymbolAddress((void**)&tilep, g_tile);
    cudaGetSymbolAddress((void**)&ecol, g_ecol);
    cudaGetSymbolAddress((void**)&eval, g_eval);

    // ---------------- CSR build: 5 live structures --------------------------
    Segs S;
    {
        int eb = 0, k = 0;
        auto seg = [&](const int* key, const int* other, const float* val,
                       int rbase, int nnz) {
            S.key[k] = key; S.other[k] = other; S.val[k] = val;
            S.ebase[k] = eb; S.rbase[k] = rbase;
            eb += nnz; k++;
        };
        seg(adj_row[0], adj_col[0], adj_val[0], RB_ADJ0, 320000);
        seg(adj_row[1], adj_col[1], adj_val[1], RB_ADJ1, 960000);
        seg(inc_row[0], inc_col[0], inc_val[0], RB_H2L0, 240000);  // inc1 h2l
        seg(inc_col[0], inc_row[0], inc_val[0], RB_L2H0, 240000);  // inc1 l2h
        seg(inc_row[1], inc_col[1], inc_val[1], RB_H2L1, 240000);  // inc2 h2l
        S.ebase[5] = eb;  // == ETOT
    }
    cudaMemsetAsync(cnt, 0, RTOT * sizeof(int));
    cudaMemsetAsync(cursor, 0, RTOT * sizeof(int));
    {
        int blocks = (ETOT + 255) / 256;
        hist_k<<<blocks, 256>>>(S, cnt);
        scan1<<<NTILES, 256>>>(cnt, tilep);
        scan2<<<1, 1024>>>(tilep);
        scan3<<<NTILES, 256>>>(cnt, tilep, startp);
        scatter_k<<<blocks, 256>>>(S, startp, cursor, ecol, eval);
    }

    const int GSMEM = WCHUNK * (int)sizeof(float2);  // 67584 B
    cudaFuncSetAttribute(gemm_all, cudaFuncAttributeMaxDynamicSharedMemorySize,
                         GSMEM);
    const int WMAT = 128 * 128;

    // ---------------- layer 1: 5 live GEMMs + gather ------------------------
    {
        GemmJobs P;
        P.sig = 0;
        int nj = 0, tot = 0;
        auto add = [&](const float* X, const float* W, int yoff, int M) {
            P.j[nj].X = X; P.j[nj].W = W;
            P.j[nj].Y = gy + (size_t)yoff * C128;
            P.j[nj].M = M; P.j[nj].tile0 = tot;
            tot += (M + 127) / 128; nj++;
        };
        add(x_in[0], W_same + (size_t)0 * WMAT, Y_SAME0, N0);          // l=0,r=0
        add(x_in[1], W_same + (size_t)1 * WMAT, Y_SAME1, N1);          // l=0,r=1
        add(x_in[1], W_h2l  + (size_t)0 * WMAT, Y_H2L0, N1);           // l=0,i=0
        add(x_in[0], W_l2h  + (size_t)0 * WMAT, Y_L2H0, N0);           // l=0,i=0
        add(x_in[2], W_h2l  + (size_t)1 * WMAT, Y_H2L1, N2);           // l=0,i=1
        P.njobs = nj; P.tot = tot;
        int grid = tot < 296 ? tot : 296;
        gemm_all<<<grid, 256, GSMEM>>>(P);

        int gblocks = (160000 * 32 + 255) / 256;
        gather_l1<<<gblocks, 256>>>(startp, ecol, eval, gy, gm);
    }

    // ---------------- layer 2: 2 live GEMMs + gather ------------------------
    {
        GemmJobs P;
        P.sig = 1;  // inputs are sigmoid(m)
        int nj = 0, tot = 0;
        auto add = [&](const float* X, const float* W, int yoff, int M) {
            P.j[nj].X = X; P.j[nj].W = W;
            P.j[nj].Y = gy + (size_t)yoff * C128;
            P.j[nj].M = M; P.j[nj].tile0 = tot;
            tot += (M + 127) / 128; nj++;
        };
        // m0 rows [0,40k), m1 rows [40k,160k)
        add(gm,                         W_same + (size_t)(4 + 0) * WMAT, 0, N0);
        add(gm + (size_t)40000 * C128,  W_h2l  + (size_t)(3 + 0) * WMAT, 40000, N1);
        P.njobs = nj; P.tot = tot;
        int grid = tot < 296 ? tot : 296;
        gemm_all<<<grid, 256, GSMEM>>>(P);

        int gblocks = (40000 * 32 + 255) / 256;
        gather_l2<<<gblocks, 256>>>(startp, ecol, eval, gy, gm);
    }

    // ---------------- head: softmax(sigmoid(m2) @ W_out + b_out) ------------
    int blocks = (N0 * 32 + 255) / 256;
    head_k<<<blocks, 256>>>(gm + (size_t)160000 * C128, W_out, b_out, out, N0);
}